// round 1
// baseline (speedup 1.0000x reference)
#include <cuda_runtime.h>

// CQT via combined time-domain kernels.
//   Stage 1 (k1): Cmb[b,n] = (kr@wcos - ki@wsin, kr@wsin + ki@wcos)  [96 x 2048] fp32x2
//                 (k-split over 2 partial buffers for occupancy)
//   Stage 2 (k2): reduce partials, transpose to [n][b] packed u64 for cp.async
//   Stage 3 (k3): cqt[b,f] = | sum_n x[f*512+n] * Cmb[b,n] |   (f32x2 packed FMA)

#define NF      16381      // number of frames
#define NBINS   84
#define NBP     96         // padded bins
#define KLEN    1025
#define FFTLEN  2048
#define HOP     512

typedef unsigned long long ull;

__device__ __forceinline__ ull pk2(float a, float b) {
    ull r; asm("mov.b64 %0, {%1, %2};" : "=l"(r) : "f"(a), "f"(b)); return r;
}
__device__ __forceinline__ ull ffma2(ull a, ull b, ull c) {
    ull d; asm("fma.rn.f32x2 %0, %1, %2, %3;" : "=l"(d) : "l"(a), "l"(b), "l"(c)); return d;
}
__device__ __forceinline__ float2 upk2(ull v) {
    float2 f; asm("mov.b64 {%0, %1}, %2;" : "=f"(f.x), "=f"(f.y) : "l"(v)); return f;
}
__device__ __forceinline__ float getc(const float4& v, int j) {
    return j == 0 ? v.x : (j == 1 ? v.y : (j == 2 ? v.z : v.w));
}

// Scratch (static device globals: no allocation allowed)
__device__ float2 g_part[2][NBP * FFTLEN];   // [z][b*2048+n], valid only b<84
__device__ ull    g_cmbT[FFTLEN * NBP];      // [n*96+b], packed (Cr,Ci)

// ---------------------------------------------------------------------------
// Stage 1: partial combined kernels. grid(16, 6, 2) x 256 threads.
// Block tile: 16 bins x 128 n. Thread: 2 bins x 4 n. k range split by blockIdx.z.
// ---------------------------------------------------------------------------
__device__ __forceinline__ void k1_step(ull acc[2][4], float kra, float krb,
                                        float kia, float kib, float4 c4, float4 s4) {
    ull krda = pk2(kra, kra), krdb = pk2(krb, krb);
    ull kida = pk2(-kia, kia), kidb = pk2(-kib, kib);
    float cs[4] = {c4.x, c4.y, c4.z, c4.w};
    float ss[4] = {s4.x, s4.y, s4.z, s4.w};
#pragma unroll
    for (int j = 0; j < 4; j++) {
        ull wa = pk2(cs[j], ss[j]);   // (cos, sin)
        ull wb = pk2(ss[j], cs[j]);   // (sin, cos)
        acc[0][j] = ffma2(krda, wa, acc[0][j]);   // += ( kr*c,  kr*s)
        acc[0][j] = ffma2(kida, wb, acc[0][j]);   // += (-ki*s,  ki*c)
        acc[1][j] = ffma2(krdb, wa, acc[1][j]);
        acc[1][j] = ffma2(kidb, wb, acc[1][j]);
    }
}

__global__ __launch_bounds__(256) void k1_combine(const float* __restrict__ kr,
                                                  const float* __restrict__ ki,
                                                  const float* __restrict__ wc,
                                                  const float* __restrict__ ws) {
    int tid = threadIdx.x;
    int bt = tid >> 5, nt = tid & 31;
    int b0 = blockIdx.y * 16 + bt * 2;
    if (b0 >= NBINS) return;                       // pad bins: nothing to do
    int n0 = blockIdx.x * 128 + nt * 4;
    int z = blockIdx.z;
    int k = z ? 512 : 0;
    int kend = z ? KLEN : 512;

    const float* kr0 = kr + (size_t)b0 * KLEN;
    const float* kr1 = kr0 + KLEN;
    const float* ki0 = ki + (size_t)b0 * KLEN;
    const float* ki1 = ki0 + KLEN;

    ull acc[2][4];
#pragma unroll
    for (int i = 0; i < 2; i++)
#pragma unroll
        for (int j = 0; j < 4; j++) acc[i][j] = 0ull;

    for (; k + 4 <= kend; k += 4) {
#pragma unroll
        for (int j = 0; j < 4; j++) {
            float4 c4 = *(const float4*)(wc + (size_t)(k + j) * FFTLEN + n0);
            float4 s4 = *(const float4*)(ws + (size_t)(k + j) * FFTLEN + n0);
            k1_step(acc, kr0[k + j], kr1[k + j], ki0[k + j], ki1[k + j], c4, s4);
        }
    }
    for (; k < kend; k++) {
        float4 c4 = *(const float4*)(wc + (size_t)k * FFTLEN + n0);
        float4 s4 = *(const float4*)(ws + (size_t)k * FFTLEN + n0);
        k1_step(acc, kr0[k], kr1[k], ki0[k], ki1[k], c4, s4);
    }

#pragma unroll
    for (int i = 0; i < 2; i++)
#pragma unroll
        for (int j = 0; j < 4; j++)
            g_part[z][(size_t)(b0 + i) * FFTLEN + n0 + j] = upk2(acc[i][j]);
}

// ---------------------------------------------------------------------------
// Stage 2: fold k-split partials, zero pad bins, transpose to [n][b] u64.
// ---------------------------------------------------------------------------
__global__ __launch_bounds__(256) void k2_reduce() {
    int idx = blockIdx.x * 256 + threadIdx.x;   // over 2048*96
    if (idx >= FFTLEN * NBP) return;
    int n = idx / NBP, b = idx % NBP;
    float2 v = make_float2(0.f, 0.f);
    if (b < NBINS) {
        float2 p = g_part[0][(size_t)b * FFTLEN + n];
        float2 q = g_part[1][(size_t)b * FFTLEN + n];
        v.x = p.x + q.x;
        v.y = p.y + q.y;
    }
    g_cmbT[idx] = pk2(v.x, v.y);
}

// ---------------------------------------------------------------------------
// Stage 3: main correlation GEMM.
// grid(256) x 256 threads. Block: 96 bins x 64 frames. Thread: 6 bins x 4 frames.
// A (combined kernels) via cp.async double-buffered smem; x via direct LDG.128.
// Accumulators are packed (re,im) f32x2 -> one FFMA2 per (b,f,k).
// ---------------------------------------------------------------------------
#define KC 16            // k per chunk
#define NCHUNK (FFTLEN / KC)   // 128
#define CHUNK_BYTES (KC * NBP * 8)   // 12288

__global__ __launch_bounds__(256, 2) void k3_cqt(const float* __restrict__ x,
                                                 float* __restrict__ out) {
    __shared__ ull As[2][KC][NBP];   // 24.6 KB

    int tid = threadIdx.x;
    int ft = tid & 15;       // frame-thread  (16)
    int bt = tid >> 4;       // bin-thread    (16)
    int f0 = blockIdx.x * 64;
    int b0 = bt * 6;

    const char* srcbase = (const char*)g_cmbT;

    auto issue = [&](int c) {
        unsigned sbase = (unsigned)__cvta_generic_to_shared(&As[c & 1][0][0]);
        const char* g = srcbase + (size_t)c * CHUNK_BYTES;
#pragma unroll
        for (int w = 0; w < 3; w++) {
            int idx = tid + w * 256;     // 768 x 16B = one chunk
            asm volatile("cp.async.cg.shared.global [%0], [%1], 16;"
                         :: "r"(sbase + idx * 16), "l"(g + (size_t)idx * 16));
        }
        asm volatile("cp.async.commit_group;" ::: "memory");
    };

    // Per-thread frame base offsets into x (clamped so OOB frames read valid mem)
    size_t xoff[4];
#pragma unroll
    for (int r = 0; r < 4; r++) {
        int f = f0 + ft * 4 + r;
        if (f > NF - 1) f = NF - 1;
        xoff[r] = (size_t)f * HOP;
    }

    ull acc[6][4];
#pragma unroll
    for (int i = 0; i < 6; i++)
#pragma unroll
        for (int r = 0; r < 4; r++) acc[i][r] = 0ull;

    issue(0);

    for (int c = 0; c < NCHUNK; c++) {
        if (c + 1 < NCHUNK) {
            issue(c + 1);
            asm volatile("cp.async.wait_group 1;" ::: "memory");
        } else {
            asm volatile("cp.async.wait_group 0;" ::: "memory");
        }
        __syncthreads();

        const ull(&A)[KC][NBP] = As[c & 1];
        float4 xv[4];
#pragma unroll
        for (int kk = 0; kk < KC; kk++) {
            if ((kk & 3) == 0) {
#pragma unroll
                for (int r = 0; r < 4; r++)
                    xv[r] = *(const float4*)(x + xoff[r] + c * KC + kk);
            }
            ulonglong2 A01 = *(const ulonglong2*)&A[kk][b0];
            ulonglong2 A23 = *(const ulonglong2*)&A[kk][b0 + 2];
            ulonglong2 A45 = *(const ulonglong2*)&A[kk][b0 + 4];
            ull a[6] = {A01.x, A01.y, A23.x, A23.y, A45.x, A45.y};
            ull bd[4];
#pragma unroll
            for (int r = 0; r < 4; r++) {
                float v = getc(xv[r], kk & 3);
                bd[r] = pk2(v, v);
            }
#pragma unroll
            for (int i = 0; i < 6; i++)
#pragma unroll
                for (int r = 0; r < 4; r++)
                    acc[i][r] = ffma2(a[i], bd[r], acc[i][r]);
        }
        __syncthreads();
    }

    // Epilogue: magnitude + store
#pragma unroll
    for (int i = 0; i < 6; i++) {
        int b = b0 + i;
#pragma unroll
        for (int r = 0; r < 4; r++) {
            int f = f0 + ft * 4 + r;
            if (b < NBINS && f < NF) {
                float2 v = upk2(acc[i][r]);
                out[(size_t)b * NF + f] = sqrtf(v.x * v.x + v.y * v.y);
            }
        }
    }
}

// ---------------------------------------------------------------------------
extern "C" void kernel_launch(void* const* d_in, const int* in_sizes, int n_in,
                              void* d_out, int out_size) {
    const float* x    = (const float*)d_in[0];
    const float* wcos = (const float*)d_in[1];
    const float* wsin = (const float*)d_in[2];
    const float* kr   = (const float*)d_in[3];
    const float* ki   = (const float*)d_in[4];
    float* out = (float*)d_out;

    k1_combine<<<dim3(16, 6, 2), 256>>>(kr, ki, wcos, wsin);
    k2_reduce<<<(FFTLEN * NBP + 255) / 256, 256>>>();
    k3_cqt<<<256, 256>>>(x, out);
}

// round 2
// speedup vs baseline: 1.6115x; 1.6115x over previous
#include <cuda_runtime.h>

// CQT via combined time-domain kernels (fp32, packed f32x2 math).
//   k1: Cmb[b,n] = (kr@wcos - ki@wsin, kr@wsin + ki@wcos), n-pair packed, 8-way k-split
//   k2: fold partials -> g_cmbT[n][b] packed (re,im) u64
//   k3: cqt[b,f] = | sum_n x[f*512+n] * Cmb[b,n] |, x staged via smem (no scattered LDG)

#define NF      16381
#define NBINS   84
#define NBP     96
#define KLEN    1025
#define FFTLEN  2048
#define HOP     512

typedef unsigned long long ull;

__device__ __forceinline__ ull pk2(float a, float b) {
    ull r; asm("mov.b64 %0, {%1, %2};" : "=l"(r) : "f"(a), "f"(b)); return r;
}
__device__ __forceinline__ ull ffma2(ull a, ull b, ull c) {
    ull d; asm("fma.rn.f32x2 %0, %1, %2, %3;" : "=l"(d) : "l"(a), "l"(b), "l"(c)); return d;
}
__device__ __forceinline__ float2 upk2(ull v) {
    float2 f; asm("mov.b64 {%0, %1}, %2;" : "=f"(f.x), "=f"(f.y) : "l"(v)); return f;
}

#define KSPLIT 8
__device__ float2 g_part[KSPLIT][NBP * FFTLEN];   // [z][b*2048+n]
__device__ ull    g_cmbT[FFTLEN * NBP];           // [n*96+b] packed (re,im)

// ---------------------------------------------------------------------------
// k1: grid(8, 6, 8) x 256. Thread: 2 bins x 8 n (4 n-pairs re + 4 im).
// w pairs load directly as ulonglong2 -> only 6 packing MOVs per k.
// ---------------------------------------------------------------------------
__global__ __launch_bounds__(256) void k1_combine(const float* __restrict__ kr,
                                                  const float* __restrict__ ki,
                                                  const float* __restrict__ wc,
                                                  const float* __restrict__ ws) {
    int tid = threadIdx.x;
    int nt = tid & 31, bt = tid >> 5;
    int b0 = blockIdx.y * 16 + bt * 2;
    if (b0 >= NBINS) return;
    int n0 = blockIdx.x * 256 + nt * 8;
    int z = blockIdx.z;
    int k = z * 128;
    int kend = (z == KSPLIT - 1) ? KLEN : k + 128;

    const float* krA = kr + (size_t)b0 * KLEN;
    const float* krB = krA + KLEN;
    const float* kiA = ki + (size_t)b0 * KLEN;
    const float* kiB = kiA + KLEN;

    ull accr[2][4], acci[2][4];
#pragma unroll
    for (int i = 0; i < 2; i++)
#pragma unroll
        for (int j = 0; j < 4; j++) { accr[i][j] = 0ull; acci[i][j] = 0ull; }

    for (; k < kend; k++) {
        const ull* wcp = (const ull*)(wc + (size_t)k * FFTLEN + n0);
        const ull* wsp = (const ull*)(ws + (size_t)k * FFTLEN + n0);
        ulonglong2 c01 = *(const ulonglong2*)wcp;
        ulonglong2 c23 = *(const ulonglong2*)(wcp + 2);
        ulonglong2 s01 = *(const ulonglong2*)wsp;
        ulonglong2 s23 = *(const ulonglong2*)(wsp + 2);
        ull cp[4] = {c01.x, c01.y, c23.x, c23.y};
        ull sp[4] = {s01.x, s01.y, s23.x, s23.y};

        float ra = __ldg(krA + k), rb = __ldg(krB + k);
        float ia = __ldg(kiA + k), ib = __ldg(kiB + k);
        ull krdA = pk2(ra, ra), krdB = pk2(rb, rb);
        ull kinA = pk2(-ia, -ia), kinB = pk2(-ib, -ib);
        ull kipA = pk2(ia, ia), kipB = pk2(ib, ib);

#pragma unroll
        for (int j = 0; j < 4; j++) {
            accr[0][j] = ffma2(krdA, cp[j], accr[0][j]);
            accr[0][j] = ffma2(kinA, sp[j], accr[0][j]);
            acci[0][j] = ffma2(krdA, sp[j], acci[0][j]);
            acci[0][j] = ffma2(kipA, cp[j], acci[0][j]);
            accr[1][j] = ffma2(krdB, cp[j], accr[1][j]);
            accr[1][j] = ffma2(kinB, sp[j], accr[1][j]);
            acci[1][j] = ffma2(krdB, sp[j], acci[1][j]);
            acci[1][j] = ffma2(kipB, cp[j], acci[1][j]);
        }
    }

#pragma unroll
    for (int i = 0; i < 2; i++)
#pragma unroll
        for (int j = 0; j < 4; j++) {
            float2 r = upk2(accr[i][j]);
            float2 m = upk2(acci[i][j]);
            float4 v = make_float4(r.x, m.x, r.y, m.y);  // (re,im) for n, n+1
            *(float4*)&g_part[z][(size_t)(b0 + i) * FFTLEN + n0 + 2 * j] = v;
        }
}

// ---------------------------------------------------------------------------
// k2: fold 8 partials, zero pad bins, transpose to [n][b] u64.
// ---------------------------------------------------------------------------
__global__ __launch_bounds__(256) void k2_reduce() {
    int idx = blockIdx.x * 256 + threadIdx.x;
    if (idx >= FFTLEN * NBP) return;
    int n = idx / NBP, b = idx % NBP;
    float re = 0.f, im = 0.f;
    if (b < NBINS) {
#pragma unroll
        for (int z = 0; z < KSPLIT; z++) {
            float2 p = g_part[z][(size_t)b * FFTLEN + n];
            re += p.x; im += p.y;
        }
    }
    g_cmbT[idx] = pk2(re, im);
}

// ---------------------------------------------------------------------------
// k3: grid(296) x 224. Block: 96 bins x 56 frames. Thread: 6 bins x 4 frames.
// A via cp.async double-buffer; x cooperatively loaded + duplicate-packed to smem.
// Inner loop: 5 LDS.128 + 24 FFMA2 per k. No LDG, no MOV packs.
// ---------------------------------------------------------------------------
#define FT 56
#define K3T 224
#define KC 16
#define NCHUNK (FFTLEN / KC)            // 128
#define CHUNK16 (KC * NBP * 8 / 16)     // 768 16-byte units

__global__ __launch_bounds__(K3T, 2) void k3_cqt(const float* __restrict__ x,
                                                 float* __restrict__ out) {
    __shared__ ull As[2][KC][NBP];      // 24576 B
    __shared__ ull Xd[2][KC][FT];       // 14336 B

    int tid = threadIdx.x;
    int bt = tid / 14;          // 0..15  -> 6 bins each
    int ft = tid % 14;          // 0..13  -> 4 frames each
    int b0 = bt * 6;
    int f0 = blockIdx.x * FT;

    // x-loader role: frame fl (0..55), quarter q (0..3)
    int fl = tid >> 2, q = tid & 3;
    int fload = f0 + fl; if (fload > NF - 1) fload = NF - 1;
    const float* xp = x + (size_t)fload * HOP + q * 4;

    auto issueA = [&](int c) {
        unsigned sb = (unsigned)__cvta_generic_to_shared(&As[c & 1][0][0]);
        const char* g = (const char*)g_cmbT + (size_t)c * (KC * NBP * 8);
        for (int idx = tid; idx < CHUNK16; idx += K3T) {
            asm volatile("cp.async.cg.shared.global [%0], [%1], 16;"
                         :: "r"(sb + idx * 16), "l"(g + (size_t)idx * 16));
        }
        asm volatile("cp.async.commit_group;" ::: "memory");
    };

    ull acc[6][4];
#pragma unroll
    for (int i = 0; i < 6; i++)
#pragma unroll
        for (int r = 0; r < 4; r++) acc[i][r] = 0ull;

    issueA(0);
    float4 xr = *(const float4*)xp;     // chunk 0 slice

    for (int c = 0; c < NCHUNK; c++) {
        asm volatile("cp.async.wait_group 0;" ::: "memory");
        // duplicate-pack this thread's x slice into Xd(c)
        {
            float xs[4] = {xr.x, xr.y, xr.z, xr.w};
#pragma unroll
            for (int t = 0; t < 4; t++)
                Xd[c & 1][q * 4 + t][fl] = pk2(xs[t], xs[t]);
        }
        __syncthreads();

        if (c + 1 < NCHUNK) {
            issueA(c + 1);
            xr = *(const float4*)(xp + (c + 1) * KC);
        }

        const ull(&A)[KC][NBP] = As[c & 1];
        const ull(&X)[KC][FT] = Xd[c & 1];
#pragma unroll
        for (int kk = 0; kk < KC; kk++) {
            ulonglong2 a01 = *(const ulonglong2*)&A[kk][b0];
            ulonglong2 a23 = *(const ulonglong2*)&A[kk][b0 + 2];
            ulonglong2 a45 = *(const ulonglong2*)&A[kk][b0 + 4];
            ulonglong2 x01 = *(const ulonglong2*)&X[kk][ft * 4];
            ulonglong2 x23 = *(const ulonglong2*)&X[kk][ft * 4 + 2];
            ull a[6] = {a01.x, a01.y, a23.x, a23.y, a45.x, a45.y};
            ull bd[4] = {x01.x, x01.y, x23.x, x23.y};
#pragma unroll
            for (int i = 0; i < 6; i++)
#pragma unroll
                for (int r = 0; r < 4; r++)
                    acc[i][r] = ffma2(a[i], bd[r], acc[i][r]);
        }
        __syncthreads();
    }

    // epilogue: magnitude + masked store
#pragma unroll
    for (int i = 0; i < 6; i++) {
        int b = b0 + i;
#pragma unroll
        for (int r = 0; r < 4; r++) {
            int f = f0 + ft * 4 + r;
            if (b < NBINS && f < NF) {
                float2 v = upk2(acc[i][r]);
                out[(size_t)b * NF + f] = sqrtf(v.x * v.x + v.y * v.y);
            }
        }
    }
}

// ---------------------------------------------------------------------------
extern "C" void kernel_launch(void* const* d_in, const int* in_sizes, int n_in,
                              void* d_out, int out_size) {
    const float* x    = (const float*)d_in[0];
    const float* wcos = (const float*)d_in[1];
    const float* wsin = (const float*)d_in[2];
    const float* kr   = (const float*)d_in[3];
    const float* ki   = (const float*)d_in[4];
    float* out = (float*)d_out;

    k1_combine<<<dim3(8, 6, KSPLIT), 256>>>(kr, ki, wcos, wsin);
    k2_reduce<<<(FFTLEN * NBP + 255) / 256, 256>>>();
    k3_cqt<<<296, K3T>>>(x, out);
}

// round 5
// speedup vs baseline: 2.7168x; 1.6859x over previous
#include <cuda_runtime.h>
#include <cuda_bf16.h>
#include <cstdint>

#define NF      16381
#define NBINS   84
#define KLEN    1025
#define FFTLEN  2048
#define HOP     512
#define NSAMP   8388608
#define XPAD    (NSAMP + 2048)

typedef unsigned long long ull;

__device__ __forceinline__ ull pk2(float a, float b) {
    ull r; asm("mov.b64 %0, {%1, %2};" : "=l"(r) : "f"(a), "f"(b)); return r;
}
__device__ __forceinline__ ull ffma2(ull a, ull b, ull c) {
    ull d; asm("fma.rn.f32x2 %0, %1, %2, %3;" : "=l"(d) : "l"(a), "l"(b), "l"(c)); return d;
}
__device__ __forceinline__ float2 upk2(ull v) {
    float2 f; asm("mov.b64 {%0, %1}, %2;" : "=f"(f.x), "=f"(f.y) : "l"(v)); return f;
}
__device__ __forceinline__ uint32_t smem_u32(const void* p) {
    uint32_t a; asm("{ .reg .u64 t; cvta.to.shared.u64 t, %1; cvt.u32.u64 %0, t; }" : "=r"(a) : "l"(p));
    return a;
}

// ---------------- scratch globals ----------------
#define KSPLIT 16
__device__ float2 g_part[KSPLIT][96 * FFTLEN];       // k1 partials [z][b*2048+n]
__device__ __nv_bfloat16 g_xhi[XPAD];
__device__ __nv_bfloat16 g_xlo[XPAD];

#define NROW 192                                     // B rows: 168 used (84 bins x re/im)
__device__ __nv_bfloat16 g_B[2][NROW * FFTLEN];      // [hi/lo][row][k] row-major

// ---------------------------------------------------------------------------
// k1: combined kernels Cmb[b,n] = (kr@wc - ki@ws, kr@ws + ki@wc), 16-way k-split
// ---------------------------------------------------------------------------
__global__ __launch_bounds__(256) void k1_combine(const float* __restrict__ kr,
                                                  const float* __restrict__ ki,
                                                  const float* __restrict__ wc,
                                                  const float* __restrict__ ws) {
    int tid = threadIdx.x;
    int nt = tid & 31, bt = tid >> 5;
    int b0 = blockIdx.y * 16 + bt * 2;
    if (b0 >= NBINS) return;
    int n0 = blockIdx.x * 256 + nt * 8;
    int z = blockIdx.z;
    int k = z * 64;
    int kend = (z == KSPLIT - 1) ? KLEN : k + 64;

    const float* krA = kr + (size_t)b0 * KLEN;
    const float* krB = krA + KLEN;
    const float* kiA = ki + (size_t)b0 * KLEN;
    const float* kiB = kiA + KLEN;

    ull accr[2][4], acci[2][4];
#pragma unroll
    for (int i = 0; i < 2; i++)
#pragma unroll
        for (int j = 0; j < 4; j++) { accr[i][j] = 0ull; acci[i][j] = 0ull; }

#pragma unroll 2
    for (; k < kend; k++) {
        const ull* wcp = (const ull*)(wc + (size_t)k * FFTLEN + n0);
        const ull* wsp = (const ull*)(ws + (size_t)k * FFTLEN + n0);
        ulonglong2 c01 = *(const ulonglong2*)wcp;
        ulonglong2 c23 = *(const ulonglong2*)(wcp + 2);
        ulonglong2 s01 = *(const ulonglong2*)wsp;
        ulonglong2 s23 = *(const ulonglong2*)(wsp + 2);
        ull cp[4] = {c01.x, c01.y, c23.x, c23.y};
        ull sp[4] = {s01.x, s01.y, s23.x, s23.y};

        float ra = __ldg(krA + k), rb = __ldg(krB + k);
        float ia = __ldg(kiA + k), ib = __ldg(kiB + k);
        ull krdA = pk2(ra, ra), krdB = pk2(rb, rb);
        ull kinA = pk2(-ia, -ia), kinB = pk2(-ib, -ib);
        ull kipA = pk2(ia, ia), kipB = pk2(ib, ib);

#pragma unroll
        for (int j = 0; j < 4; j++) {
            accr[0][j] = ffma2(krdA, cp[j], accr[0][j]);
            accr[0][j] = ffma2(kinA, sp[j], accr[0][j]);
            acci[0][j] = ffma2(krdA, sp[j], acci[0][j]);
            acci[0][j] = ffma2(kipA, cp[j], acci[0][j]);
            accr[1][j] = ffma2(krdB, cp[j], accr[1][j]);
            accr[1][j] = ffma2(kinB, sp[j], accr[1][j]);
            acci[1][j] = ffma2(krdB, sp[j], acci[1][j]);
            acci[1][j] = ffma2(kipB, cp[j], acci[1][j]);
        }
    }

#pragma unroll
    for (int i = 0; i < 2; i++)
#pragma unroll
        for (int j = 0; j < 4; j++) {
            float2 r = upk2(accr[i][j]);
            float2 m = upk2(acci[i][j]);
            float4 v = make_float4(r.x, m.x, r.y, m.y);
            *(float4*)&g_part[z][(size_t)(b0 + i) * FFTLEN + n0 + 2 * j] = v;
        }
}

// ---------------------------------------------------------------------------
// kx: split x into bf16 hi/lo with zero pad tail
// ---------------------------------------------------------------------------
__global__ __launch_bounds__(256) void kx_split(const float* __restrict__ x) {
    size_t base = ((size_t)blockIdx.x * 256 + threadIdx.x) * 4;
    if (base >= XPAD) return;
    float4 v = make_float4(0.f, 0.f, 0.f, 0.f);
    if (base + 4 <= NSAMP) v = *(const float4*)(x + base);
    float vs[4] = {v.x, v.y, v.z, v.w};
    ushort4 h, l;
    unsigned short* hp = &h.x;
    unsigned short* lp = &l.x;
#pragma unroll
    for (int t = 0; t < 4; t++) {
        __nv_bfloat16 bh = __float2bfloat16(vs[t]);
        __nv_bfloat16 bl = __float2bfloat16(vs[t] - __bfloat162float(bh));
        hp[t] = __bfloat16_as_ushort(bh);
        lp[t] = __bfloat16_as_ushort(bl);
    }
    *(ushort4*)(g_xhi + base) = h;
    *(ushort4*)(g_xlo + base) = l;
}

// ---------------------------------------------------------------------------
// k2: fold k1 partials, hi/lo split -> g_B[img][row][k].  row 2b = Cr, 2b+1 = Ci.
// ---------------------------------------------------------------------------
__global__ __launch_bounds__(256) void k2_pack() {
    int gid = blockIdx.x * 256 + threadIdx.x;   // over 192*256
    int j = gid >> 8;                            // row 0..191
    int n0 = (gid & 255) << 3;
    float v[8];
#pragma unroll
    for (int t = 0; t < 8; t++) v[t] = 0.f;
    if (j < 2 * NBINS) {
        int b = j >> 1, im = j & 1;
#pragma unroll
        for (int z = 0; z < KSPLIT; z++) {
            const float2* p = &g_part[z][(size_t)b * FFTLEN + n0];
#pragma unroll
            for (int t = 0; t < 8; t++) v[t] += im ? p[t].y : p[t].x;
        }
    }
    ushort4 hq[2], lq[2];
    unsigned short* hp = &hq[0].x;
    unsigned short* lp = &lq[0].x;
#pragma unroll
    for (int t = 0; t < 8; t++) {
        __nv_bfloat16 bh = __float2bfloat16(v[t]);
        __nv_bfloat16 bl = __float2bfloat16(v[t] - __bfloat162float(bh));
        hp[t] = __bfloat16_as_ushort(bh);
        lp[t] = __bfloat16_as_ushort(bl);
    }
    *(uint4*)&g_B[0][(size_t)j * FFTLEN + n0] = *(uint4*)&hq[0];
    *(uint4*)&g_B[1][(size_t)j * FFTLEN + n0] = *(uint4*)&lq[0];
}

// ---------------------------------------------------------------------------
// k3: warp-level bf16 HMMA GEMM.
// D[128 frames, 192 rows] = sum over 3 segments of A[128,2048] x B[192,2048]^T
// CTA: 512 thr = 16 warps (4M x 4N). Warp tile 32x48. K chunk = 32.
// cp.async double buffer, 80-byte padded smem rows (ldmatrix conflict-free).
// ---------------------------------------------------------------------------
#define K3T 512
#define KCH 32
#define NCHSEG (FFTLEN / KCH)     // 64
#define NCHUNK (3 * NCHSEG)       // 192
#define ROWB 80                   // padded smem row stride (bytes)
#define A_SM (128 * ROWB)         // 10240
#define B_SM (NROW * ROWB)        // 15360
#define STAGE (A_SM + B_SM)       // 25600
#define K3_SMEM (2 * STAGE)       // 51200

__device__ __forceinline__ void ldsm4(uint32_t* r, uint32_t addr) {
    asm volatile("ldmatrix.sync.aligned.m8n8.x4.shared.b16 {%0,%1,%2,%3}, [%4];"
                 : "=r"(r[0]), "=r"(r[1]), "=r"(r[2]), "=r"(r[3]) : "r"(addr));
}
__device__ __forceinline__ void hmma(float* d, const uint32_t* a, uint32_t b0, uint32_t b1) {
    asm volatile("mma.sync.aligned.m16n8k16.row.col.f32.bf16.bf16.f32 "
                 "{%0,%1,%2,%3}, {%4,%5,%6,%7}, {%8,%9}, {%0,%1,%2,%3};"
                 : "+f"(d[0]), "+f"(d[1]), "+f"(d[2]), "+f"(d[3])
                 : "r"(a[0]), "r"(a[1]), "r"(a[2]), "r"(a[3]), "r"(b0), "r"(b1));
}
__device__ __forceinline__ void cp16(uint32_t dst, const void* src) {
    asm volatile("cp.async.cg.shared.global [%0], [%1], 16;" :: "r"(dst), "l"(src));
}

__global__ __launch_bounds__(K3T, 1) void k3_cqt(float* __restrict__ out) {
    extern __shared__ __align__(16) char dsm[];
    uint32_t sb = smem_u32(dsm);

    int tid = threadIdx.x;
    int lane = tid & 31, wid = tid >> 5;
    int wm = wid & 3, wn = wid >> 2;
    int f0 = blockIdx.x * 128;

    // cp.async roles
    int arow = tid >> 2, aq = tid & 3;                 // A: 512 x 16B
    int brow0 = tid >> 2, brow1 = (tid + 512) >> 2;    // B: 768 x 16B (two waves)

    auto issue = [&](int c) {
        int s = c & 1;
        int seg = c / NCHSEG;
        int n0 = (c % NCHSEG) * KCH;
        const __nv_bfloat16* xs = (seg == 1) ? g_xlo : g_xhi;
        const __nv_bfloat16* bi = g_B[seg == 2 ? 1 : 0];
        uint32_t ab = sb + s * STAGE;
        uint32_t bbase = ab + A_SM;
        cp16(ab + arow * ROWB + aq * 16,
             xs + (size_t)(f0 + arow) * HOP + n0 + aq * 8);
        cp16(bbase + brow0 * ROWB + aq * 16,
             bi + (size_t)brow0 * FFTLEN + n0 + aq * 8);
        if (brow1 < NROW)
            cp16(bbase + brow1 * ROWB + aq * 16,
                 bi + (size_t)brow1 * FFTLEN + n0 + aq * 8);
        asm volatile("cp.async.commit_group;" ::: "memory");
    };

    float acc[2][6][4];
#pragma unroll
    for (int mi = 0; mi < 2; mi++)
#pragma unroll
        for (int nj = 0; nj < 6; nj++)
#pragma unroll
            for (int t = 0; t < 4; t++) acc[mi][nj][t] = 0.f;

    // ldmatrix lane addressing
    int lrow8 = ((lane >> 3) & 1) * 8 + (lane & 7);    // row within 16-row group
    int lkh = (lane >> 4) * 16;                        // 0 or 16 bytes (k half)

    issue(0);

    for (int c = 0; c < NCHUNK; c++) {
        if (c + 1 < NCHUNK) {
            issue(c + 1);
            asm volatile("cp.async.wait_group 1;" ::: "memory");
        } else {
            asm volatile("cp.async.wait_group 0;" ::: "memory");
        }
        __syncthreads();

        int s = c & 1;
        uint32_t ab = sb + s * STAGE;
        uint32_t bbase = ab + A_SM;

#pragma unroll
        for (int h = 0; h < 2; h++) {                  // two k16 steps
            uint32_t af[2][4], bf[3][4];
#pragma unroll
            for (int mi = 0; mi < 2; mi++)
                ldsm4(af[mi], ab + (wm * 32 + mi * 16 + lrow8) * ROWB + h * 32 + lkh);
#pragma unroll
            for (int ni = 0; ni < 3; ni++)
                ldsm4(bf[ni], bbase + (wn * 48 + ni * 16 + lrow8) * ROWB + h * 32 + lkh);
#pragma unroll
            for (int mi = 0; mi < 2; mi++)
#pragma unroll
                for (int nj = 0; nj < 6; nj++) {
                    int ni = nj >> 1, half = nj & 1;
                    hmma(acc[mi][nj], af[mi], bf[ni][half], bf[ni][half + 2]);
                }
        }
        __syncthreads();
    }

    // epilogue: magnitude + store
#pragma unroll
    for (int mi = 0; mi < 2; mi++)
#pragma unroll
        for (int nj = 0; nj < 6; nj++) {
            int n_even = wn * 48 + nj * 8 + (lane & 3) * 2;
            int b = n_even >> 1;
            int fA = f0 + wm * 32 + mi * 16 + (lane >> 2);
            if (b < NBINS) {
                if (fA < NF) {
                    float re = acc[mi][nj][0], im = acc[mi][nj][1];
                    out[(size_t)b * NF + fA] = sqrtf(re * re + im * im);
                }
                if (fA + 8 < NF) {
                    float re = acc[mi][nj][2], im = acc[mi][nj][3];
                    out[(size_t)b * NF + fA + 8] = sqrtf(re * re + im * im);
                }
            }
        }
}

// ---------------------------------------------------------------------------
extern "C" void kernel_launch(void* const* d_in, const int* in_sizes, int n_in,
                              void* d_out, int out_size) {
    const float* x    = (const float*)d_in[0];
    const float* wcos = (const float*)d_in[1];
    const float* wsin = (const float*)d_in[2];
    const float* kr   = (const float*)d_in[3];
    const float* ki   = (const float*)d_in[4];
    float* out = (float*)d_out;

    static int smem_set = 0;
    if (!smem_set) {
        cudaFuncSetAttribute(k3_cqt, cudaFuncAttributeMaxDynamicSharedMemorySize, K3_SMEM);
        smem_set = 1;
    }

    kx_split<<<(XPAD / 4 + 255) / 256, 256>>>(x);
    k1_combine<<<dim3(8, 6, KSPLIT), 256>>>(kr, ki, wcos, wsin);
    k2_pack<<<192, 256>>>();
    k3_cqt<<<128, K3T, K3_SMEM>>>(out);
}

// round 6
// speedup vs baseline: 2.8561x; 1.0513x over previous
#include <cuda_runtime.h>
#include <cuda_bf16.h>
#include <cstdint>

#define NF      16381
#define NBINS   84
#define KLEN    1025
#define FFTLEN  2048
#define HOP     512
#define NSAMP   8388608
#define XPAD    (NSAMP + 2048)

typedef unsigned long long ull;

__device__ __forceinline__ ull pk2(float a, float b) {
    ull r; asm("mov.b64 %0, {%1, %2};" : "=l"(r) : "f"(a), "f"(b)); return r;
}
__device__ __forceinline__ ull ffma2(ull a, ull b, ull c) {
    ull d; asm("fma.rn.f32x2 %0, %1, %2, %3;" : "=l"(d) : "l"(a), "l"(b), "l"(c)); return d;
}
__device__ __forceinline__ float2 upk2(ull v) {
    float2 f; asm("mov.b64 {%0, %1}, %2;" : "=f"(f.x), "=f"(f.y) : "l"(v)); return f;
}
__device__ __forceinline__ uint32_t smem_u32(const void* p) {
    uint32_t a; asm("{ .reg .u64 t; cvta.to.shared.u64 t, %1; cvt.u32.u64 %0, t; }" : "=r"(a) : "l"(p));
    return a;
}

// ---------------- scratch globals ----------------
#define KSPLIT 8
__device__ float2 g_part[KSPLIT][96 * FFTLEN];       // k1 partials [z][b*2048+n]
__device__ __nv_bfloat16 g_xhi[XPAD];
__device__ __nv_bfloat16 g_xlo[XPAD];

#define NROW 192                                     // B rows: 168 used (84 bins x re/im)
__device__ __nv_bfloat16 g_B[2][NROW * FFTLEN];      // [hi/lo][row][k] row-major

// ---------------------------------------------------------------------------
// k1: combined kernels Cmb[b,n] = (kr@wc - ki@ws, kr@ws + ki@wc)
// grid(16, 3, 8) x 256.  Thread: 4 bins x 4 n.  2 LDG.128 per k for 32 FFMA2.
// ---------------------------------------------------------------------------
__global__ __launch_bounds__(256) void k1_combine(const float* __restrict__ kr,
                                                  const float* __restrict__ ki,
                                                  const float* __restrict__ wc,
                                                  const float* __restrict__ ws) {
    int tid = threadIdx.x;
    int nt = tid & 31, bt = tid >> 5;
    int b0 = blockIdx.y * 32 + bt * 4;
    if (b0 >= NBINS) return;
    int n0 = blockIdx.x * 128 + nt * 4;
    int z = blockIdx.z;
    int k = z * 128;
    int kend = (z == KSPLIT - 1) ? KLEN : k + 128;

    const float* krp = kr + (size_t)b0 * KLEN;
    const float* kip = ki + (size_t)b0 * KLEN;

    ull accr[4][2], acci[4][2];
#pragma unroll
    for (int i = 0; i < 4; i++)
#pragma unroll
        for (int j = 0; j < 2; j++) { accr[i][j] = 0ull; acci[i][j] = 0ull; }

#pragma unroll 2
    for (; k < kend; k++) {
        ulonglong2 c2 = *(const ulonglong2*)(wc + (size_t)k * FFTLEN + n0);
        ulonglong2 s2 = *(const ulonglong2*)(ws + (size_t)k * FFTLEN + n0);
        ull cp[2] = {c2.x, c2.y};
        ull sp[2] = {s2.x, s2.y};
#pragma unroll
        for (int i = 0; i < 4; i++) {
            float r  = __ldg(krp + (size_t)i * KLEN + k);
            float im = __ldg(kip + (size_t)i * KLEN + k);
            ull krd = pk2(r, r), kin = pk2(-im, -im), kp = pk2(im, im);
#pragma unroll
            for (int j = 0; j < 2; j++) {
                accr[i][j] = ffma2(krd, cp[j], accr[i][j]);
                accr[i][j] = ffma2(kin, sp[j], accr[i][j]);
                acci[i][j] = ffma2(krd, sp[j], acci[i][j]);
                acci[i][j] = ffma2(kp,  cp[j], acci[i][j]);
            }
        }
    }

#pragma unroll
    for (int i = 0; i < 4; i++)
#pragma unroll
        for (int j = 0; j < 2; j++) {
            float2 r = upk2(accr[i][j]);
            float2 m = upk2(acci[i][j]);
            float4 v = make_float4(r.x, m.x, r.y, m.y);
            *(float4*)&g_part[z][(size_t)(b0 + i) * FFTLEN + n0 + 2 * j] = v;
        }
}

// ---------------------------------------------------------------------------
// kx: split x into bf16 hi/lo with zero pad tail
// ---------------------------------------------------------------------------
__global__ __launch_bounds__(256) void kx_split(const float* __restrict__ x) {
    size_t base = ((size_t)blockIdx.x * 256 + threadIdx.x) * 4;
    if (base >= XPAD) return;
    float4 v = make_float4(0.f, 0.f, 0.f, 0.f);
    if (base + 4 <= NSAMP) v = *(const float4*)(x + base);
    float vs[4] = {v.x, v.y, v.z, v.w};
    ushort4 h, l;
    unsigned short* hp = &h.x;
    unsigned short* lp = &l.x;
#pragma unroll
    for (int t = 0; t < 4; t++) {
        __nv_bfloat16 bh = __float2bfloat16(vs[t]);
        __nv_bfloat16 bl = __float2bfloat16(vs[t] - __bfloat162float(bh));
        hp[t] = __bfloat16_as_ushort(bh);
        lp[t] = __bfloat16_as_ushort(bl);
    }
    *(ushort4*)(g_xhi + base) = h;
    *(ushort4*)(g_xlo + base) = l;
}

// ---------------------------------------------------------------------------
// k2: fold k1 partials, hi/lo split -> g_B[img][row][k].  row 2b = Cr, 2b+1 = Ci.
// ---------------------------------------------------------------------------
__global__ __launch_bounds__(256) void k2_pack() {
    int gid = blockIdx.x * 256 + threadIdx.x;   // over 192*256
    int j = gid >> 8;                            // row 0..191
    int n0 = (gid & 255) << 3;
    float v[8];
#pragma unroll
    for (int t = 0; t < 8; t++) v[t] = 0.f;
    if (j < 2 * NBINS) {
        int b = j >> 1, im = j & 1;
#pragma unroll
        for (int z = 0; z < KSPLIT; z++) {
            const float2* p = &g_part[z][(size_t)b * FFTLEN + n0];
#pragma unroll
            for (int t = 0; t < 8; t++) v[t] += im ? p[t].y : p[t].x;
        }
    }
    ushort4 hq[2], lq[2];
    unsigned short* hp = &hq[0].x;
    unsigned short* lp = &lq[0].x;
#pragma unroll
    for (int t = 0; t < 8; t++) {
        __nv_bfloat16 bh = __float2bfloat16(v[t]);
        __nv_bfloat16 bl = __float2bfloat16(v[t] - __bfloat162float(bh));
        hp[t] = __bfloat16_as_ushort(bh);
        lp[t] = __bfloat16_as_ushort(bl);
    }
    *(uint4*)&g_B[0][(size_t)j * FFTLEN + n0] = *(uint4*)&hq[0];
    *(uint4*)&g_B[1][(size_t)j * FFTLEN + n0] = *(uint4*)&lq[0];
}

// ---------------------------------------------------------------------------
// k3: warp-level bf16 HMMA GEMM, 3-stage cp.async pipeline, 1 sync per chunk.
// D[64 frames, 192 rows] per CTA; grid 256; 256 thr = 8 warps (2M x 4N),
// warp tile 32x48.  80-byte padded smem rows (ldmatrix conflict-free).
// ---------------------------------------------------------------------------
#define K3T 256
#define KCH 32
#define NCHSEG (FFTLEN / KCH)     // 64
#define NCHUNK (3 * NCHSEG)       // 192
#define ROWB 80
#define CTAM 64
#define A_SM (CTAM * ROWB)        // 5120
#define B_SM (NROW * ROWB)        // 15360
#define STAGE (A_SM + B_SM)       // 20480
#define K3_SMEM (3 * STAGE)       // 61440

__device__ __forceinline__ void ldsm4(uint32_t* r, uint32_t addr) {
    asm volatile("ldmatrix.sync.aligned.m8n8.x4.shared.b16 {%0,%1,%2,%3}, [%4];"
                 : "=r"(r[0]), "=r"(r[1]), "=r"(r[2]), "=r"(r[3]) : "r"(addr));
}
__device__ __forceinline__ void hmma(float* d, const uint32_t* a, uint32_t b0, uint32_t b1) {
    asm volatile("mma.sync.aligned.m16n8k16.row.col.f32.bf16.bf16.f32 "
                 "{%0,%1,%2,%3}, {%4,%5,%6,%7}, {%8,%9}, {%0,%1,%2,%3};"
                 : "+f"(d[0]), "+f"(d[1]), "+f"(d[2]), "+f"(d[3])
                 : "r"(a[0]), "r"(a[1]), "r"(a[2]), "r"(a[3]), "r"(b0), "r"(b1));
}
__device__ __forceinline__ void cp16(uint32_t dst, const void* src) {
    asm volatile("cp.async.cg.shared.global [%0], [%1], 16;" :: "r"(dst), "l"(src));
}

__global__ __launch_bounds__(K3T, 2) void k3_cqt(float* __restrict__ out) {
    extern __shared__ __align__(16) char dsm[];
    uint32_t sb = smem_u32(dsm);

    int tid = threadIdx.x;
    int lane = tid & 31, wid = tid >> 5;
    int wm = wid & 1, wn = wid >> 1;
    int f0 = blockIdx.x * CTAM;

    // cp.async roles: A = 256 x 16B (1/thread), B = 768 x 16B (3/thread)
    int arow = tid >> 2, aq = tid & 3;

    auto issue = [&](int c) {
        int s = c % 3;
        int seg = c / NCHSEG;
        int n0 = (c % NCHSEG) * KCH;
        const __nv_bfloat16* xs = (seg == 1) ? g_xlo : g_xhi;
        const __nv_bfloat16* bi = g_B[seg == 2 ? 1 : 0];
        uint32_t ab = sb + s * STAGE;
        cp16(ab + arow * ROWB + aq * 16,
             xs + (size_t)(f0 + arow) * HOP + n0 + aq * 8);
        uint32_t bb = ab + A_SM;
#pragma unroll
        for (int w = 0; w < 3; w++) {
            int u = tid + w * 256;
            int row = u >> 2, q = u & 3;
            cp16(bb + row * ROWB + q * 16,
                 bi + (size_t)row * FFTLEN + n0 + q * 8);
        }
        asm volatile("cp.async.commit_group;" ::: "memory");
    };

    float acc[2][6][4];
#pragma unroll
    for (int mi = 0; mi < 2; mi++)
#pragma unroll
        for (int nj = 0; nj < 6; nj++)
#pragma unroll
            for (int t = 0; t < 4; t++) acc[mi][nj][t] = 0.f;

    int lrow8 = ((lane >> 3) & 1) * 8 + (lane & 7);
    int lkh = (lane >> 4) * 16;

    issue(0);
    issue(1);

    for (int c = 0; c < NCHUNK; c++) {
        if (c + 1 < NCHUNK) {
            asm volatile("cp.async.wait_group 1;" ::: "memory");
        } else {
            asm volatile("cp.async.wait_group 0;" ::: "memory");
        }
        __syncthreads();
        if (c + 2 < NCHUNK) issue(c + 2);

        uint32_t ab = sb + (c % 3) * STAGE;
        uint32_t bb = ab + A_SM;

#pragma unroll
        for (int h = 0; h < 2; h++) {
            uint32_t af[2][4], bf[3][4];
#pragma unroll
            for (int mi = 0; mi < 2; mi++)
                ldsm4(af[mi], ab + (wm * 32 + mi * 16 + lrow8) * ROWB + h * 32 + lkh);
#pragma unroll
            for (int ni = 0; ni < 3; ni++)
                ldsm4(bf[ni], bb + (wn * 48 + ni * 16 + lrow8) * ROWB + h * 32 + lkh);
#pragma unroll
            for (int mi = 0; mi < 2; mi++)
#pragma unroll
                for (int nj = 0; nj < 6; nj++) {
                    int ni = nj >> 1, half = nj & 1;
                    hmma(acc[mi][nj], af[mi], bf[ni][half], bf[ni][half + 2]);
                }
        }
    }

    // epilogue: magnitude + store
#pragma unroll
    for (int mi = 0; mi < 2; mi++)
#pragma unroll
        for (int nj = 0; nj < 6; nj++) {
            int n_even = wn * 48 + nj * 8 + (lane & 3) * 2;
            int b = n_even >> 1;
            int fA = f0 + wm * 32 + mi * 16 + (lane >> 2);
            if (b < NBINS) {
                if (fA < NF) {
                    float re = acc[mi][nj][0], im = acc[mi][nj][1];
                    out[(size_t)b * NF + fA] = sqrtf(re * re + im * im);
                }
                if (fA + 8 < NF) {
                    float re = acc[mi][nj][2], im = acc[mi][nj][3];
                    out[(size_t)b * NF + fA + 8] = sqrtf(re * re + im * im);
                }
            }
        }
}

// ---------------------------------------------------------------------------
extern "C" void kernel_launch(void* const* d_in, const int* in_sizes, int n_in,
                              void* d_out, int out_size) {
    const float* x    = (const float*)d_in[0];
    const float* wcos = (const float*)d_in[1];
    const float* wsin = (const float*)d_in[2];
    const float* kr   = (const float*)d_in[3];
    const float* ki   = (const float*)d_in[4];
    float* out = (float*)d_out;

    static int smem_set = 0;
    if (!smem_set) {
        cudaFuncSetAttribute(k3_cqt, cudaFuncAttributeMaxDynamicSharedMemorySize, K3_SMEM);
        smem_set = 1;
    }

    kx_split<<<(XPAD / 4 + 255) / 256, 256>>>(x);
    k1_combine<<<dim3(16, 3, KSPLIT), 256>>>(kr, ki, wcos, wsin);
    k2_pack<<<192, 256>>>();
    k3_cqt<<<256, K3T, K3_SMEM>>>(out);
}

// round 7
// speedup vs baseline: 2.9908x; 1.0472x over previous
#include <cuda_runtime.h>
#include <cuda_bf16.h>
#include <cstdint>

#define NF      16381
#define NBINS   84
#define KLEN    1025
#define FFTLEN  2048
#define HOP     512
#define NSAMP   8388608
#define XPAD    (NSAMP + 2048)

typedef unsigned long long ull;

__device__ __forceinline__ ull pk2(float a, float b) {
    ull r; asm("mov.b64 %0, {%1, %2};" : "=l"(r) : "f"(a), "f"(b)); return r;
}
__device__ __forceinline__ ull ffma2(ull a, ull b, ull c) {
    ull d; asm("fma.rn.f32x2 %0, %1, %2, %3;" : "=l"(d) : "l"(a), "l"(b), "l"(c)); return d;
}
__device__ __forceinline__ float2 upk2(ull v) {
    float2 f; asm("mov.b64 {%0, %1}, %2;" : "=f"(f.x), "=f"(f.y) : "l"(v)); return f;
}
__device__ __forceinline__ uint32_t smem_u32(const void* p) {
    uint32_t a; asm("{ .reg .u64 t; cvta.to.shared.u64 t, %1; cvt.u32.u64 %0, t; }" : "=r"(a) : "l"(p));
    return a;
}

// ---------------- scratch globals ----------------
#define KSPLIT 8
__device__ float2 g_part[KSPLIT][96 * FFTLEN];       // k1 partials [z][b*2048+n]
__device__ __nv_bfloat16 g_xhi[XPAD];
__device__ __nv_bfloat16 g_xlo[XPAD];

#define NROW 192                                     // B rows: 168 used (84 bins x re/im)
__device__ __nv_bfloat16 g_B[2][NROW * FFTLEN];      // [hi/lo][row][k] row-major

// ---------------------------------------------------------------------------
// k1: combined kernels Cmb[b,n] = (kr@wc - ki@ws, kr@ws + ki@wc)
// grid(16, 3, 8) x 256.  Thread: 4 bins x 4 n.
// ---------------------------------------------------------------------------
__global__ __launch_bounds__(256) void k1_combine(const float* __restrict__ kr,
                                                  const float* __restrict__ ki,
                                                  const float* __restrict__ wc,
                                                  const float* __restrict__ ws) {
    int tid = threadIdx.x;
    int nt = tid & 31, bt = tid >> 5;
    int b0 = blockIdx.y * 32 + bt * 4;
    if (b0 >= NBINS) return;
    int n0 = blockIdx.x * 128 + nt * 4;
    int z = blockIdx.z;
    int k = z * 128;
    int kend = (z == KSPLIT - 1) ? KLEN : k + 128;

    const float* krp = kr + (size_t)b0 * KLEN;
    const float* kip = ki + (size_t)b0 * KLEN;

    ull accr[4][2], acci[4][2];
#pragma unroll
    for (int i = 0; i < 4; i++)
#pragma unroll
        for (int j = 0; j < 2; j++) { accr[i][j] = 0ull; acci[i][j] = 0ull; }

#pragma unroll 4
    for (; k < kend; k++) {
        ulonglong2 c2 = *(const ulonglong2*)(wc + (size_t)k * FFTLEN + n0);
        ulonglong2 s2 = *(const ulonglong2*)(ws + (size_t)k * FFTLEN + n0);
        ull cp[2] = {c2.x, c2.y};
        ull sp[2] = {s2.x, s2.y};
#pragma unroll
        for (int i = 0; i < 4; i++) {
            float r  = __ldg(krp + (size_t)i * KLEN + k);
            float im = __ldg(kip + (size_t)i * KLEN + k);
            ull krd = pk2(r, r), kin = pk2(-im, -im), kp = pk2(im, im);
#pragma unroll
            for (int j = 0; j < 2; j++) {
                accr[i][j] = ffma2(krd, cp[j], accr[i][j]);
                accr[i][j] = ffma2(kin, sp[j], accr[i][j]);
                acci[i][j] = ffma2(krd, sp[j], acci[i][j]);
                acci[i][j] = ffma2(kp,  cp[j], acci[i][j]);
            }
        }
    }

#pragma unroll
    for (int i = 0; i < 4; i++)
#pragma unroll
        for (int j = 0; j < 2; j++) {
            float2 r = upk2(accr[i][j]);
            float2 m = upk2(acci[i][j]);
            float4 v = make_float4(r.x, m.x, r.y, m.y);
            *(float4*)&g_part[z][(size_t)(b0 + i) * FFTLEN + n0 + 2 * j] = v;
        }
}

// ---------------------------------------------------------------------------
// kx: split x into bf16 hi/lo with zero pad tail
// ---------------------------------------------------------------------------
__global__ __launch_bounds__(256) void kx_split(const float* __restrict__ x) {
    size_t base = ((size_t)blockIdx.x * 256 + threadIdx.x) * 4;
    if (base >= XPAD) return;
    float4 v = make_float4(0.f, 0.f, 0.f, 0.f);
    if (base + 4 <= NSAMP) v = *(const float4*)(x + base);
    float vs[4] = {v.x, v.y, v.z, v.w};
    ushort4 h, l;
    unsigned short* hp = &h.x;
    unsigned short* lp = &l.x;
#pragma unroll
    for (int t = 0; t < 4; t++) {
        __nv_bfloat16 bh = __float2bfloat16(vs[t]);
        __nv_bfloat16 bl = __float2bfloat16(vs[t] - __bfloat162float(bh));
        hp[t] = __bfloat16_as_ushort(bh);
        lp[t] = __bfloat16_as_ushort(bl);
    }
    *(ushort4*)(g_xhi + base) = h;
    *(ushort4*)(g_xlo + base) = l;
}

// ---------------------------------------------------------------------------
// k2: fold k1 partials, hi/lo split -> g_B[img][row][k].  row 2b = Cr, 2b+1 = Ci.
// ---------------------------------------------------------------------------
__global__ __launch_bounds__(256) void k2_pack() {
    int gid = blockIdx.x * 256 + threadIdx.x;
    int j = gid >> 8;
    int n0 = (gid & 255) << 3;
    float v[8];
#pragma unroll
    for (int t = 0; t < 8; t++) v[t] = 0.f;
    if (j < 2 * NBINS) {
        int b = j >> 1, im = j & 1;
#pragma unroll
        for (int z = 0; z < KSPLIT; z++) {
            const float2* p = &g_part[z][(size_t)b * FFTLEN + n0];
#pragma unroll
            for (int t = 0; t < 8; t++) v[t] += im ? p[t].y : p[t].x;
        }
    }
    ushort4 hq[2], lq[2];
    unsigned short* hp = &hq[0].x;
    unsigned short* lp = &lq[0].x;
#pragma unroll
    for (int t = 0; t < 8; t++) {
        __nv_bfloat16 bh = __float2bfloat16(v[t]);
        __nv_bfloat16 bl = __float2bfloat16(v[t] - __bfloat162float(bh));
        hp[t] = __bfloat16_as_ushort(bh);
        lp[t] = __bfloat16_as_ushort(bl);
    }
    *(uint4*)&g_B[0][(size_t)j * FFTLEN + n0] = *(uint4*)&hq[0];
    *(uint4*)&g_B[1][(size_t)j * FFTLEN + n0] = *(uint4*)&lq[0];
}

// ---------------------------------------------------------------------------
// k3: warp HMMA GEMM, 4-stage cp.async ring + register frag double-buffering.
// CTA: 64 frames x 192 rows, 8 warps (2M x 4N), warp tile 32x48.
// Per k16-step: 5 ldsm prefetch (next step) overlapped with 12 HMMA (this step).
// wait_group -> __syncthreads -> issue ordering makes arrivals CTA-visible.
// ---------------------------------------------------------------------------
#define K3T 256
#define KCH 32
#define NCHSEG (FFTLEN / KCH)     // 64
#define NCHUNK (3 * NCHSEG)       // 192
#define ROWB 80
#define CTAM 64
#define A_SM (CTAM * ROWB)        // 5120
#define B_SM (NROW * ROWB)        // 15360
#define STAGE (A_SM + B_SM)       // 20480
#define NSTAGE 4
#define K3_SMEM (NSTAGE * STAGE)  // 81920

__device__ __forceinline__ void ldsm4(uint32_t* r, uint32_t addr) {
    asm volatile("ldmatrix.sync.aligned.m8n8.x4.shared.b16 {%0,%1,%2,%3}, [%4];"
                 : "=r"(r[0]), "=r"(r[1]), "=r"(r[2]), "=r"(r[3]) : "r"(addr));
}
__device__ __forceinline__ void hmma(float* d, const uint32_t* a, uint32_t b0, uint32_t b1) {
    asm volatile("mma.sync.aligned.m16n8k16.row.col.f32.bf16.bf16.f32 "
                 "{%0,%1,%2,%3}, {%4,%5,%6,%7}, {%8,%9}, {%0,%1,%2,%3};"
                 : "+f"(d[0]), "+f"(d[1]), "+f"(d[2]), "+f"(d[3])
                 : "r"(a[0]), "r"(a[1]), "r"(a[2]), "r"(a[3]), "r"(b0), "r"(b1));
}
__device__ __forceinline__ void cp16(uint32_t dst, const void* src) {
    asm volatile("cp.async.cg.shared.global [%0], [%1], 16;" :: "r"(dst), "l"(src));
}

__global__ __launch_bounds__(K3T, 2) void k3_cqt(float* __restrict__ out) {
    extern __shared__ __align__(16) char dsm[];
    uint32_t sb = smem_u32(dsm);

    int tid = threadIdx.x;
    int lane = tid & 31, wid = tid >> 5;
    int wm = wid & 1, wn = wid >> 1;
    int f0 = blockIdx.x * CTAM;

    int arow = tid >> 2, aq = tid & 3;

    auto issue = [&](int c) {
        int s = c & 3;
        int seg = c / NCHSEG;
        int n0 = (c % NCHSEG) * KCH;
        const __nv_bfloat16* xs = (seg == 1) ? g_xlo : g_xhi;
        const __nv_bfloat16* bi = g_B[seg == 2 ? 1 : 0];
        uint32_t ab = sb + s * STAGE;
        cp16(ab + arow * ROWB + aq * 16,
             xs + (size_t)(f0 + arow) * HOP + n0 + aq * 8);
        uint32_t bb = ab + A_SM;
#pragma unroll
        for (int w = 0; w < 3; w++) {
            int u = tid + w * 256;
            int row = u >> 2, q = u & 3;
            cp16(bb + row * ROWB + q * 16,
                 bi + (size_t)row * FFTLEN + n0 + q * 8);
        }
        asm volatile("cp.async.commit_group;" ::: "memory");
    };

    float acc[2][6][4];
#pragma unroll
    for (int mi = 0; mi < 2; mi++)
#pragma unroll
        for (int nj = 0; nj < 6; nj++)
#pragma unroll
            for (int t = 0; t < 4; t++) acc[mi][nj][t] = 0.f;

    int lrow8 = ((lane >> 3) & 1) * 8 + (lane & 7);
    int lkh = (lane >> 4) * 16;
    // per-warp base offsets (stage-relative)
    uint32_t aoff = (wm * 32 + lrow8) * ROWB + lkh;          // + mi*16*ROWB + h*32
    uint32_t boff = A_SM + (wn * 48 + lrow8) * ROWB + lkh;   // + ni*16*ROWB + h*32

    issue(0); issue(1); issue(2); issue(3);
    asm volatile("cp.async.wait_group 2;" ::: "memory");   // chunks 0,1 arrived (this warp)
    __syncthreads();                                        // CTA-visible

    uint32_t af0[2][4], bf0[3][4], af1[2][4], bf1[3][4];
    {
        uint32_t ab = sb;  // stage 0, h0
#pragma unroll
        for (int mi = 0; mi < 2; mi++) ldsm4(af0[mi], ab + aoff + mi * 16 * ROWB);
#pragma unroll
        for (int ni = 0; ni < 3; ni++) ldsm4(bf0[ni], ab + boff + ni * 16 * ROWB);
    }

    for (int c = 0; c < NCHUNK; c++) {
        uint32_t ab  = sb + (c & 3) * STAGE;
        uint32_t ab1 = sb + ((c + 1) & 3) * STAGE;

        // h0: prefetch (c,h1) into buf1, compute buf0
#pragma unroll
        for (int mi = 0; mi < 2; mi++) ldsm4(af1[mi], ab + aoff + mi * 16 * ROWB + 32);
#pragma unroll
        for (int ni = 0; ni < 3; ni++) ldsm4(bf1[ni], ab + boff + ni * 16 * ROWB + 32);
#pragma unroll
        for (int mi = 0; mi < 2; mi++)
#pragma unroll
            for (int nj = 0; nj < 6; nj++) {
                int ni = nj >> 1, half = nj & 1;
                hmma(acc[mi][nj], af0[mi], bf0[ni][half], bf0[ni][half + 2]);
            }

        // h1: prefetch (c+1,h0) into buf0, compute buf1
        if (c + 1 < NCHUNK) {
#pragma unroll
            for (int mi = 0; mi < 2; mi++) ldsm4(af0[mi], ab1 + aoff + mi * 16 * ROWB);
#pragma unroll
            for (int ni = 0; ni < 3; ni++) ldsm4(bf0[ni], ab1 + boff + ni * 16 * ROWB);
        }
#pragma unroll
        for (int mi = 0; mi < 2; mi++)
#pragma unroll
            for (int nj = 0; nj < 6; nj++) {
                int ni = nj >> 1, half = nj & 1;
                hmma(acc[mi][nj], af1[mi], bf1[ni][half], bf1[ni][half + 2]);
            }

        // pipeline bookkeeping: own-arrival -> CTA barrier -> refill freed stage
        if (c + 4 < NCHUNK) {
            asm volatile("cp.async.wait_group 1;" ::: "memory");
            __syncthreads();
            issue(c + 4);
        } else {
            asm volatile("cp.async.wait_group 0;" ::: "memory");
            __syncthreads();
        }
    }

    // epilogue: magnitude + store
#pragma unroll
    for (int mi = 0; mi < 2; mi++)
#pragma unroll
        for (int nj = 0; nj < 6; nj++) {
            int n_even = wn * 48 + nj * 8 + (lane & 3) * 2;
            int b = n_even >> 1;
            int fA = f0 + wm * 32 + mi * 16 + (lane >> 2);
            if (b < NBINS) {
                if (fA < NF) {
                    float re = acc[mi][nj][0], im = acc[mi][nj][1];
                    out[(size_t)b * NF + fA] = sqrtf(re * re + im * im);
                }
                if (fA + 8 < NF) {
                    float re = acc[mi][nj][2], im = acc[mi][nj][3];
                    out[(size_t)b * NF + fA + 8] = sqrtf(re * re + im * im);
                }
            }
        }
}

// ---------------------------------------------------------------------------
extern "C" void kernel_launch(void* const* d_in, const int* in_sizes, int n_in,
                              void* d_out, int out_size) {
    const float* x    = (const float*)d_in[0];
    const float* wcos = (const float*)d_in[1];
    const float* wsin = (const float*)d_in[2];
    const float* kr   = (const float*)d_in[3];
    const float* ki   = (const float*)d_in[4];
    float* out = (float*)d_out;

    static int smem_set = 0;
    if (!smem_set) {
        cudaFuncSetAttribute(k3_cqt, cudaFuncAttributeMaxDynamicSharedMemorySize, K3_SMEM);
        smem_set = 1;
    }

    kx_split<<<(XPAD / 4 + 255) / 256, 256>>>(x);
    k1_combine<<<dim3(16, 3, KSPLIT), 256>>>(kr, ki, wcos, wsin);
    k2_pack<<<192, 256>>>();
    k3_cqt<<<256, K3T, K3_SMEM>>>(out);
}